// round 8
// baseline (speedup 1.0000x reference)
#include <cuda_runtime.h>

#define BN 2
#define NN 512
#define TT 24
#define HH 8
#define DD 8
#define EE 64
#define SCALE 0.125f
#define LOG2E 1.44269504088896340736f

typedef unsigned long long u64;

// Intermediate per-head attention output (b, n, t, e) before output projection.
__device__ float g_mid[BN * NN * TT * EE];

__device__ __forceinline__ float fast_exp2(float x) {
    float y;
    asm("ex2.approx.f32 %0, %1;" : "=f"(y) : "f"(x));
    return y;
}
__device__ __forceinline__ u64 pack2(float a, float b) {
    u64 r; asm("mov.b64 %0, {%1, %2};" : "=l"(r) : "f"(a), "f"(b)); return r;
}
__device__ __forceinline__ void unpack2(u64 v, float& a, float& b) {
    asm("mov.b64 {%0, %1}, %2;" : "=f"(a), "=f"(b) : "l"(v));
}
__device__ __forceinline__ u64 fma2(u64 a, u64 b, u64 c) {
    u64 d; asm("fma.rn.f32x2 %0, %1, %2, %3;" : "=l"(d) : "l"(a), "l"(b), "l"(c)); return d;
}
__device__ __forceinline__ u64 add2(u64 a, u64 b) {
    u64 d; asm("add.rn.f32x2 %0, %1, %2;" : "=l"(d) : "l"(a), "l"(b)); return d;
}

// One CTA per (b, t, h) group: 256 threads, 2 queries per thread (queries packed
// in f32x2 lanes; K/V stored duplicated in SMEM). grid = 384, occ 3 -> 24 warps/SM.
// Per-thread state: qab 16 + acc 16 + s/p 16 regs -> fits the 85-reg cap.
__global__ __launch_bounds__(256, 3) void attn_kernel(
    const float* __restrict__ Vg, const float* __restrict__ Kg, const float* __restrict__ Qg,
    const float* __restrict__ Wv, const float* __restrict__ Wk, const float* __restrict__ Wq)
{
    __shared__ u64 sKd[DD * NN];   // sKd[j*NN + k] = (k_j, k_j)   (32 KB)
    __shared__ u64 sVd[DD * NN];   // sVd[j*NN + k] = (v_j, v_j)   (32 KB)
    __shared__ float sWk[DD * DD], sWv[DD * DD], sWq[DD * DD];

    const int tid = threadIdx.x;
    const int gid = blockIdx.x;
    const int h = gid & (HH - 1);
    const int t = (gid >> 3) % TT;
    const int b = gid / (HH * TT);

    if (tid < DD * DD) {
        sWv[tid] = Wv[tid];
        sWk[tid] = Wk[tid];
        sWq[tid] = Wq[tid];
    }
    __syncthreads();

    const size_t base = ((size_t)b * NN * TT + t) * EE + (size_t)h * DD;
    const int rowstride = TT * EE;  // 1536 floats between nodes

    // ---- Project K and V for all 512 nodes; store duplicated pairs ----
    for (int r = tid; r < NN; r += 256) {
        const float4* kp = (const float4*)(Kg + base + (size_t)r * rowstride);
        const float4* vp = (const float4*)(Vg + base + (size_t)r * rowstride);
        float4 ka = kp[0], kb = kp[1];
        float4 va = vp[0], vb = vp[1];
        float kr[8] = {ka.x, ka.y, ka.z, ka.w, kb.x, kb.y, kb.z, kb.w};
        float vr[8] = {va.x, va.y, va.z, va.w, vb.x, vb.y, vb.z, vb.w};
        #pragma unroll
        for (int i = 0; i < DD; i++) {
            float sk = 0.f, sv = 0.f;
            #pragma unroll
            for (int j = 0; j < DD; j++) {
                sk = fmaf(kr[j], sWk[i * DD + j], sk);
                sv = fmaf(vr[j], sWv[i * DD + j], sv);
            }
            sKd[i * NN + r] = pack2(sk, sk);
            sVd[i * NN + r] = pack2(sv, sv);
        }
    }

    // ---- Project both queries; fold scale*log2e; pack (qA_j, qB_j) ----
    u64 qab[8];
    {
        const float4* qpA = (const float4*)(Qg + base + (size_t)tid * rowstride);
        const float4* qpB = (const float4*)(Qg + base + (size_t)(tid + 256) * rowstride);
        float4 qa0 = qpA[0], qa1 = qpA[1];
        float4 qb0 = qpB[0], qb1 = qpB[1];
        float qrA[8] = {qa0.x, qa0.y, qa0.z, qa0.w, qa1.x, qa1.y, qa1.z, qa1.w};
        float qrB[8] = {qb0.x, qb0.y, qb0.z, qb0.w, qb1.x, qb1.y, qb1.z, qb1.w};
        #pragma unroll
        for (int i = 0; i < DD; i++) {
            float sA = 0.f, sB = 0.f;
            #pragma unroll
            for (int j = 0; j < DD; j++) {
                sA = fmaf(qrA[j], sWq[i * DD + j], sA);
                sB = fmaf(qrB[j], sWq[i * DD + j], sB);
            }
            qab[i] = pack2(sA * (SCALE * LOG2E), sB * (SCALE * LOG2E));
        }
    }
    __syncthreads();

    // ---- Main loop: 4 keys / iter; queries ride the two f32x2 lanes.
    //      All SMEM reads are LDS.128 broadcasts (2 duplicated keys each).
    u64 acc[8];
    #pragma unroll
    for (int j = 0; j < 8; j++) acc[j] = 0;   // (0.f, 0.f)
    u64 lp = 0;

    #pragma unroll 2
    for (int k = 0; k < NN; k += 4) {
        u64 s0 = 0, s1 = 0, s2 = 0, s3 = 0;   // (sA(k+i), sB(k+i))
        #pragma unroll
        for (int j = 0; j < DD; j++) {
            ulonglong2 kd01 = *(const ulonglong2*)(sKd + j * NN + k);
            ulonglong2 kd23 = *(const ulonglong2*)(sKd + j * NN + k + 2);
            s0 = fma2(qab[j], kd01.x, s0);
            s1 = fma2(qab[j], kd01.y, s1);
            s2 = fma2(qab[j], kd23.x, s2);
            s3 = fma2(qab[j], kd23.y, s3);
        }
        float a0, b0, a1, b1, a2, b2, a3, b3;
        unpack2(s0, a0, b0); unpack2(s1, a1, b1);
        unpack2(s2, a2, b2); unpack2(s3, a3, b3);
        u64 p0 = pack2(fast_exp2(a0), fast_exp2(b0));
        u64 p1 = pack2(fast_exp2(a1), fast_exp2(b1));
        u64 p2 = pack2(fast_exp2(a2), fast_exp2(b2));
        u64 p3 = pack2(fast_exp2(a3), fast_exp2(b3));
        lp = add2(lp, p0); lp = add2(lp, p1);
        lp = add2(lp, p2); lp = add2(lp, p3);

        #pragma unroll
        for (int j = 0; j < DD; j++) {
            ulonglong2 vd01 = *(const ulonglong2*)(sVd + j * NN + k);
            ulonglong2 vd23 = *(const ulonglong2*)(sVd + j * NN + k + 2);
            acc[j] = fma2(p0, vd01.x, acc[j]);
            acc[j] = fma2(p1, vd01.y, acc[j]);
            acc[j] = fma2(p2, vd23.x, acc[j]);
            acc[j] = fma2(p3, vd23.y, acc[j]);
        }
    }

    // ---- Epilogue: split packed lanes, normalize, store both query rows ----
    float lA, lB;
    unpack2(lp, lA, lB);
    const float invA = 1.0f / lA;
    const float invB = 1.0f / lB;
    float oA[8], oB[8];
    #pragma unroll
    for (int j = 0; j < 8; j++) {
        float xA, xB;
        unpack2(acc[j], xA, xB);
        oA[j] = xA * invA;
        oB[j] = xB * invB;
    }
    float* opA = g_mid + base + (size_t)tid * rowstride;
    float* opB = g_mid + base + (size_t)(tid + 256) * rowstride;
    ((float4*)opA)[0] = make_float4(oA[0], oA[1], oA[2], oA[3]);
    ((float4*)opA)[1] = make_float4(oA[4], oA[5], oA[6], oA[7]);
    ((float4*)opB)[0] = make_float4(oB[0], oB[1], oB[2], oB[3]);
    ((float4*)opB)[1] = make_float4(oB[4], oB[5], oB[6], oB[7]);
}

// Output projection: y[r,:] = x[r,:] @ Wo^T + bo, R = B*N*T = 24576 rows.
// (R7 configuration, 16.6us: protected.)
#define PRPB 64
#define PXS 68
#define PWS 68

__global__ __launch_bounds__(256) void proj_kernel(
    const float* __restrict__ Wo, const float* __restrict__ bo, float* __restrict__ out)
{
    __shared__ float sWT[EE * PWS];
    __shared__ float sb[EE];
    __shared__ float sx[PRPB * PXS];

    const int tid = threadIdx.x;
    for (int idx = tid; idx < EE * EE; idx += 256) {
        int i = idx >> 6, j = idx & 63;
        sWT[j * PWS + i] = Wo[idx];
    }
    if (tid < EE) sb[tid] = bo[tid];

    const size_t rbase = (size_t)blockIdx.x * PRPB * EE;
    #pragma unroll
    for (int idx = tid * 4; idx < PRPB * EE; idx += 256 * 4) {
        float4 v = *(const float4*)(g_mid + rbase + idx);
        float* dst = sx + (idx >> 6) * PXS + (idx & 63);
        dst[0] = v.x; dst[1] = v.y; dst[2] = v.z; dst[3] = v.w;
    }
    __syncthreads();

    const int w = tid >> 5;
    const int lane = tid & 31;
    const int i0 = w * 8;

    u64 aA[4], aB[4];
    {
        u64 b01 = pack2(sb[i0 + 0], sb[i0 + 1]);
        u64 b23 = pack2(sb[i0 + 2], sb[i0 + 3]);
        u64 b45 = pack2(sb[i0 + 4], sb[i0 + 5]);
        u64 b67 = pack2(sb[i0 + 6], sb[i0 + 7]);
        aA[0] = b01; aA[1] = b23; aA[2] = b45; aA[3] = b67;
        aB[0] = b01; aB[1] = b23; aB[2] = b45; aB[3] = b67;
    }

    const float* xA = sx + lane * PXS;
    const float* xB = sx + (lane + 32) * PXS;
    #pragma unroll 4
    for (int j4 = 0; j4 < EE; j4 += 4) {
        float4 xa4 = *(const float4*)(xA + j4);
        float4 xb4 = *(const float4*)(xB + j4);
        const float xa[4] = {xa4.x, xa4.y, xa4.z, xa4.w};
        const float xb[4] = {xb4.x, xb4.y, xb4.z, xb4.w};
        #pragma unroll
        for (int jj = 0; jj < 4; jj++) {
            const ulonglong2* wp = (const ulonglong2*)(sWT + (j4 + jj) * PWS + i0);
            ulonglong2 wa = wp[0];
            ulonglong2 wb = wp[1];
            u64 xpa = pack2(xa[jj], xa[jj]);
            u64 xpb = pack2(xb[jj], xb[jj]);
            aA[0] = fma2(xpa, wa.x, aA[0]);
            aA[1] = fma2(xpa, wa.y, aA[1]);
            aA[2] = fma2(xpa, wb.x, aA[2]);
            aA[3] = fma2(xpa, wb.y, aA[3]);
            aB[0] = fma2(xpb, wa.x, aB[0]);
            aB[1] = fma2(xpb, wa.y, aB[1]);
            aB[2] = fma2(xpb, wb.x, aB[2]);
            aB[3] = fma2(xpb, wb.y, aB[3]);
        }
    }

    __syncthreads();
    #pragma unroll
    for (int r = 0; r < 2; r++) {
        const u64* a = r ? aB : aA;
        float* dst = sx + (lane + r * 32) * PXS + i0;
        #pragma unroll
        for (int c = 0; c < 4; c++) {
            float lo, hi;
            unpack2(a[c], lo, hi);
            dst[2 * c] = lo;
            dst[2 * c + 1] = hi;
        }
    }
    __syncthreads();
    #pragma unroll
    for (int idx = tid * 4; idx < PRPB * EE; idx += 256 * 4) {
        const float* src = sx + (idx >> 6) * PXS + (idx & 63);
        *(float4*)(out + rbase + idx) = make_float4(src[0], src[1], src[2], src[3]);
    }
}

extern "C" void kernel_launch(void* const* d_in, const int* in_sizes, int n_in,
                              void* d_out, int out_size)
{
    const float* values = (const float*)d_in[0];
    const float* keys   = (const float*)d_in[1];
    const float* query  = (const float*)d_in[2];
    const float* Wv     = (const float*)d_in[3];
    const float* Wk     = (const float*)d_in[4];
    const float* Wq     = (const float*)d_in[5];
    const float* Wo     = (const float*)d_in[6];
    const float* bo     = (const float*)d_in[7];

    attn_kernel<<<BN * TT * HH, 256>>>(values, keys, query, Wv, Wk, Wq);
    proj_kernel<<<BN * NN * TT / PRPB, 256>>>(Wo, bo, (float*)d_out);
}

// round 9
// speedup vs baseline: 1.2459x; 1.2459x over previous
#include <cuda_runtime.h>

#define BN 2
#define NN 512
#define TT 24
#define HH 8
#define DD 8
#define EE 64
#define SCALE 0.125f
#define LOG2E 1.44269504088896340736f

typedef unsigned long long u64;

// Intermediate per-head attention output (b, n, t, e) before output projection.
__device__ float g_mid[BN * NN * TT * EE];

__device__ __forceinline__ float fast_exp2(float x) {
    float y;
    asm("ex2.approx.f32 %0, %1;" : "=f"(y) : "f"(x));
    return y;
}
__device__ __forceinline__ u64 pack2(float a, float b) {
    u64 r; asm("mov.b64 %0, {%1, %2};" : "=l"(r) : "f"(a), "f"(b)); return r;
}
__device__ __forceinline__ void unpack2(u64 v, float& a, float& b) {
    asm("mov.b64 {%0, %1}, %2;" : "=f"(a), "=f"(b) : "l"(v));
}
__device__ __forceinline__ u64 fma2(u64 a, u64 b, u64 c) {
    u64 d; asm("fma.rn.f32x2 %0, %1, %2, %3;" : "=l"(d) : "l"(a), "l"(b), "l"(c)); return d;
}
__device__ __forceinline__ u64 add2(u64 a, u64 b) {
    u64 d; asm("add.rn.f32x2 %0, %1, %2;" : "=l"(d) : "l"(a), "l"(b)); return d;
}

// One CTA per (b, t, h) group: 256 threads, 2 queries per thread. grid = 384.
// R3 slot balance (16 LDS / 68 fma2 / 8 MUFU per 4-key iter) + explicit
// software pipelining: block k+4's scores issue before block k's exp/AV,
// hiding the unpack->ex2->pack chain with independent score FMAs.
__global__ __launch_bounds__(256, 2) void attn_kernel(
    const float* __restrict__ Vg, const float* __restrict__ Kg, const float* __restrict__ Qg,
    const float* __restrict__ Wv, const float* __restrict__ Wk, const float* __restrict__ Wq)
{
    __shared__ float sKT[DD * NN];   // sKT[j*NN + k]
    __shared__ float sVT[DD * NN];   // sVT[j*NN + k]
    __shared__ float sWk[DD * DD], sWv[DD * DD], sWq[DD * DD];

    const int tid = threadIdx.x;
    const int gid = blockIdx.x;
    const int h = gid & (HH - 1);
    const int t = (gid >> 3) % TT;
    const int b = gid / (HH * TT);

    if (tid < DD * DD) {
        sWv[tid] = Wv[tid];
        sWk[tid] = Wk[tid];
        sWq[tid] = Wq[tid];
    }
    __syncthreads();

    const size_t base = ((size_t)b * NN * TT + t) * EE + (size_t)h * DD;
    const int rowstride = TT * EE;  // 1536 floats between nodes

    // ---- Project K and V (both transposed) for all 512 nodes ----
    for (int r = tid; r < NN; r += 256) {
        const float4* kp = (const float4*)(Kg + base + (size_t)r * rowstride);
        const float4* vp = (const float4*)(Vg + base + (size_t)r * rowstride);
        float4 ka = kp[0], kb = kp[1];
        float4 va = vp[0], vb = vp[1];
        float kr[8] = {ka.x, ka.y, ka.z, ka.w, kb.x, kb.y, kb.z, kb.w};
        float vr[8] = {va.x, va.y, va.z, va.w, vb.x, vb.y, vb.z, vb.w};
        #pragma unroll
        for (int i = 0; i < DD; i++) {
            float sk = 0.f, sv = 0.f;
            #pragma unroll
            for (int j = 0; j < DD; j++) {
                sk = fmaf(kr[j], sWk[i * DD + j], sk);
                sv = fmaf(vr[j], sWv[i * DD + j], sv);
            }
            sKT[i * NN + r] = sk;    // consecutive lanes -> consecutive banks
            sVT[i * NN + r] = sv;
        }
    }

    // ---- Project both queries of this thread; fold scale*log2e; pack dup ----
    u64 qpA[8], qpB[8];
    #pragma unroll
    for (int sel = 0; sel < 2; sel++) {
        const int q = tid + sel * 256;
        const float4* qptr = (const float4*)(Qg + base + (size_t)q * rowstride);
        float4 qa = qptr[0], qb = qptr[1];
        float qr[8] = {qa.x, qa.y, qa.z, qa.w, qb.x, qb.y, qb.z, qb.w};
        #pragma unroll
        for (int i = 0; i < DD; i++) {
            float s = 0.f;
            #pragma unroll
            for (int j = 0; j < DD; j++) s = fmaf(qr[j], sWq[i * DD + j], s);
            s *= (SCALE * LOG2E);
            if (sel == 0) qpA[i] = pack2(s, s); else qpB[i] = pack2(s, s);
        }
    }
    __syncthreads();

    // Score block for keys k..k+3 (both queries), packed f32x2.
    auto scores = [&](int k, u64& sA01, u64& sA23, u64& sB01, u64& sB23) {
        sA01 = 0; sA23 = 0; sB01 = 0; sB23 = 0;
        #pragma unroll
        for (int j = 0; j < DD; j++) {
            ulonglong2 kv = *(const ulonglong2*)(sKT + j * NN + k);  // 4 keys @ dim j
            sA01 = fma2(kv.x, qpA[j], sA01);
            sA23 = fma2(kv.y, qpA[j], sA23);
            sB01 = fma2(kv.x, qpB[j], sB01);
            sB23 = fma2(kv.y, qpB[j], sB23);
        }
    };
    // exp + AV accumulation for a score block at keys k..k+3.
    u64 accA[8], accB[8];
    #pragma unroll
    for (int j = 0; j < 8; j++) { accA[j] = 0; accB[j] = 0; }
    u64 lpA = 0, lpB = 0;

    auto consume = [&](int k, u64 sA01, u64 sA23, u64 sB01, u64 sB23) {
        float a0, a1, a2, a3, b0, b1, b2, b3;
        unpack2(sA01, a0, a1); unpack2(sA23, a2, a3);
        unpack2(sB01, b0, b1); unpack2(sB23, b2, b3);
        u64 pA01 = pack2(fast_exp2(a0), fast_exp2(a1));
        u64 pA23 = pack2(fast_exp2(a2), fast_exp2(a3));
        u64 pB01 = pack2(fast_exp2(b0), fast_exp2(b1));
        u64 pB23 = pack2(fast_exp2(b2), fast_exp2(b3));
        lpA = add2(lpA, pA01); lpA = add2(lpA, pA23);
        lpB = add2(lpB, pB01); lpB = add2(lpB, pB23);
        #pragma unroll
        for (int j = 0; j < DD; j++) {
            ulonglong2 vv = *(const ulonglong2*)(sVT + j * NN + k);  // 4 keys @ dim j
            accA[j] = fma2(pA01, vv.x, accA[j]);
            accA[j] = fma2(pA23, vv.y, accA[j]);
            accB[j] = fma2(pB01, vv.x, accB[j]);
            accB[j] = fma2(pB23, vv.y, accB[j]);
        }
    };

    // ---- Software-pipelined main loop: scores(k+4) issue before consume(k) ----
    u64 cA01, cA23, cB01, cB23;
    scores(0, cA01, cA23, cB01, cB23);
    #pragma unroll 2
    for (int k = 0; k < NN - 4; k += 4) {
        u64 nA01, nA23, nB01, nB23;
        scores(k + 4, nA01, nA23, nB01, nB23);   // independent of current block
        consume(k, cA01, cA23, cB01, cB23);      // MUFU chain hides behind ^
        cA01 = nA01; cA23 = nA23; cB01 = nB01; cB23 = nB23;
    }
    consume(NN - 4, cA01, cA23, cB01, cB23);

    // ---- Epilogue: fold packed halves, normalize, store both query rows ----
    #pragma unroll
    for (int sel = 0; sel < 2; sel++) {
        const u64* acc = sel ? accB : accA;
        u64 lp = sel ? lpB : lpA;
        float l0, l1;
        unpack2(lp, l0, l1);
        const float inv = 1.0f / (l0 + l1);
        float o[8];
        #pragma unroll
        for (int j = 0; j < 8; j++) {
            float x, y;
            unpack2(acc[j], x, y);
            o[j] = (x + y) * inv;
        }
        float* op = g_mid + base + (size_t)(tid + sel * 256) * rowstride;
        ((float4*)op)[0] = make_float4(o[0], o[1], o[2], o[3]);
        ((float4*)op)[1] = make_float4(o[4], o[5], o[6], o[7]);
    }
}

// Output projection: y[r,:] = x[r,:] @ Wo^T + bo, R = B*N*T = 24576 rows.
// (R7 configuration, 16.5us: protected.)
#define PRPB 64
#define PXS 68
#define PWS 68

__global__ __launch_bounds__(256) void proj_kernel(
    const float* __restrict__ Wo, const float* __restrict__ bo, float* __restrict__ out)
{
    __shared__ float sWT[EE * PWS];
    __shared__ float sb[EE];
    __shared__ float sx[PRPB * PXS];

    const int tid = threadIdx.x;
    for (int idx = tid; idx < EE * EE; idx += 256) {
        int i = idx >> 6, j = idx & 63;
        sWT[j * PWS + i] = Wo[idx];
    }
    if (tid < EE) sb[tid] = bo[tid];

    const size_t rbase = (size_t)blockIdx.x * PRPB * EE;
    #pragma unroll
    for (int idx = tid * 4; idx < PRPB * EE; idx += 256 * 4) {
        float4 v = *(const float4*)(g_mid + rbase + idx);
        float* dst = sx + (idx >> 6) * PXS + (idx & 63);
        dst[0] = v.x; dst[1] = v.y; dst[2] = v.z; dst[3] = v.w;
    }
    __syncthreads();

    const int w = tid >> 5;
    const int lane = tid & 31;
    const int i0 = w * 8;

    u64 aA[4], aB[4];
    {
        u64 b01 = pack2(sb[i0 + 0], sb[i0 + 1]);
        u64 b23 = pack2(sb[i0 + 2], sb[i0 + 3]);
        u64 b45 = pack2(sb[i0 + 4], sb[i0 + 5]);
        u64 b67 = pack2(sb[i0 + 6], sb[i0 + 7]);
        aA[0] = b01; aA[1] = b23; aA[2] = b45; aA[3] = b67;
        aB[0] = b01; aB[1] = b23; aB[2] = b45; aB[3] = b67;
    }

    const float* xA = sx + lane * PXS;
    const float* xB = sx + (lane + 32) * PXS;
    #pragma unroll 4
    for (int j4 = 0; j4 < EE; j4 += 4) {
        float4 xa4 = *(const float4*)(xA + j4);
        float4 xb4 = *(const float4*)(xB + j4);
        const float xa[4] = {xa4.x, xa4.y, xa4.z, xa4.w};
        const float xb[4] = {xb4.x, xb4.y, xb4.z, xb4.w};
        #pragma unroll
        for (int jj = 0; jj < 4; jj++) {
            const ulonglong2* wp = (const ulonglong2*)(sWT + (j4 + jj) * PWS + i0);
            ulonglong2 wa = wp[0];
            ulonglong2 wb = wp[1];
            u64 xpa = pack2(xa[jj], xa[jj]);
            u64 xpb = pack2(xb[jj], xb[jj]);
            aA[0] = fma2(xpa, wa.x, aA[0]);
            aA[1] = fma2(xpa, wa.y, aA[1]);
            aA[2] = fma2(xpa, wb.x, aA[2]);
            aA[3] = fma2(xpa, wb.y, aA[3]);
            aB[0] = fma2(xpb, wa.x, aB[0]);
            aB[1] = fma2(xpb, wa.y, aB[1]);
            aB[2] = fma2(xpb, wb.x, aB[2]);
            aB[3] = fma2(xpb, wb.y, aB[3]);
        }
    }

    __syncthreads();
    #pragma unroll
    for (int r = 0; r < 2; r++) {
        const u64* a = r ? aB : aA;
        float* dst = sx + (lane + r * 32) * PXS + i0;
        #pragma unroll
        for (int c = 0; c < 4; c++) {
            float lo, hi;
            unpack2(a[c], lo, hi);
            dst[2 * c] = lo;
            dst[2 * c + 1] = hi;
        }
    }
    __syncthreads();
    #pragma unroll
    for (int idx = tid * 4; idx < PRPB * EE; idx += 256 * 4) {
        const float* src = sx + (idx >> 6) * PXS + (idx & 63);
        *(float4*)(out + rbase + idx) = make_float4(src[0], src[1], src[2], src[3]);
    }
}

extern "C" void kernel_launch(void* const* d_in, const int* in_sizes, int n_in,
                              void* d_out, int out_size)
{
    const float* values = (const float*)d_in[0];
    const float* keys   = (const float*)d_in[1];
    const float* query  = (const float*)d_in[2];
    const float* Wv     = (const float*)d_in[3];
    const float* Wk     = (const float*)d_in[4];
    const float* Wq     = (const float*)d_in[5];
    const float* Wo     = (const float*)d_in[6];
    const float* bo     = (const float*)d_in[7];

    attn_kernel<<<BN * TT * HH, 256>>>(values, keys, query, Wv, Wk, Wq);
    proj_kernel<<<BN * NN * TT / PRPB, 256>>>(Wo, bo, (float*)d_out);
}

// round 10
// speedup vs baseline: 1.2485x; 1.0021x over previous
#include <cuda_runtime.h>

#define BN 2
#define NN 512
#define TT 24
#define HH 8
#define DD 8
#define EE 64
#define SCALE 0.125f
#define LOG2E 1.44269504088896340736f

typedef unsigned long long u64;

// Intermediate per-head attention output (b, n, t, e) before output projection.
__device__ float g_mid[BN * NN * TT * EE];

__device__ __forceinline__ float fast_exp2(float x) {
    float y;
    asm("ex2.approx.f32 %0, %1;" : "=f"(y) : "f"(x));
    return y;
}
__device__ __forceinline__ u64 pack2(float a, float b) {
    u64 r; asm("mov.b64 %0, {%1, %2};" : "=l"(r) : "f"(a), "f"(b)); return r;
}
__device__ __forceinline__ void unpack2(u64 v, float& a, float& b) {
    asm("mov.b64 {%0, %1}, %2;" : "=f"(a), "=f"(b) : "l"(v));
}
__device__ __forceinline__ u64 fma2(u64 a, u64 b, u64 c) {
    u64 d; asm("fma.rn.f32x2 %0, %1, %2, %3;" : "=l"(d) : "l"(a), "l"(b), "l"(c)); return d;
}
__device__ __forceinline__ u64 add2(u64 a, u64 b) {
    u64 d; asm("add.rn.f32x2 %0, %1, %2;" : "=l"(d) : "l"(a), "l"(b)); return d;
}

// One CTA per (b, t, h) group: 256 threads, 2 queries per thread. grid = 384.
// R3 slot balance (16 LDS / 68 fma2 / 8 MUFU per 4-key iter) + explicit
// software pipelining: block k+4's scores issue before block k's exp/AV,
// hiding the unpack->ex2->pack chain with independent score FMAs.
__global__ __launch_bounds__(256, 2) void attn_kernel(
    const float* __restrict__ Vg, const float* __restrict__ Kg, const float* __restrict__ Qg,
    const float* __restrict__ Wv, const float* __restrict__ Wk, const float* __restrict__ Wq)
{
    __shared__ float sKT[DD * NN];   // sKT[j*NN + k]
    __shared__ float sVT[DD * NN];   // sVT[j*NN + k]
    __shared__ float sWk[DD * DD], sWv[DD * DD], sWq[DD * DD];

    const int tid = threadIdx.x;
    const int gid = blockIdx.x;
    const int h = gid & (HH - 1);
    const int t = (gid >> 3) % TT;
    const int b = gid / (HH * TT);

    if (tid < DD * DD) {
        sWv[tid] = Wv[tid];
        sWk[tid] = Wk[tid];
        sWq[tid] = Wq[tid];
    }
    __syncthreads();

    const size_t base = ((size_t)b * NN * TT + t) * EE + (size_t)h * DD;
    const int rowstride = TT * EE;  // 1536 floats between nodes

    // ---- Project K and V (both transposed) for all 512 nodes ----
    for (int r = tid; r < NN; r += 256) {
        const float4* kp = (const float4*)(Kg + base + (size_t)r * rowstride);
        const float4* vp = (const float4*)(Vg + base + (size_t)r * rowstride);
        float4 ka = kp[0], kb = kp[1];
        float4 va = vp[0], vb = vp[1];
        float kr[8] = {ka.x, ka.y, ka.z, ka.w, kb.x, kb.y, kb.z, kb.w};
        float vr[8] = {va.x, va.y, va.z, va.w, vb.x, vb.y, vb.z, vb.w};
        #pragma unroll
        for (int i = 0; i < DD; i++) {
            float sk = 0.f, sv = 0.f;
            #pragma unroll
            for (int j = 0; j < DD; j++) {
                sk = fmaf(kr[j], sWk[i * DD + j], sk);
                sv = fmaf(vr[j], sWv[i * DD + j], sv);
            }
            sKT[i * NN + r] = sk;    // consecutive lanes -> consecutive banks
            sVT[i * NN + r] = sv;
        }
    }

    // ---- Project both queries of this thread; fold scale*log2e; pack dup ----
    u64 qpA[8], qpB[8];
    #pragma unroll
    for (int sel = 0; sel < 2; sel++) {
        const int q = tid + sel * 256;
        const float4* qptr = (const float4*)(Qg + base + (size_t)q * rowstride);
        float4 qa = qptr[0], qb = qptr[1];
        float qr[8] = {qa.x, qa.y, qa.z, qa.w, qb.x, qb.y, qb.z, qb.w};
        #pragma unroll
        for (int i = 0; i < DD; i++) {
            float s = 0.f;
            #pragma unroll
            for (int j = 0; j < DD; j++) s = fmaf(qr[j], sWq[i * DD + j], s);
            s *= (SCALE * LOG2E);
            if (sel == 0) qpA[i] = pack2(s, s); else qpB[i] = pack2(s, s);
        }
    }
    __syncthreads();

    // Score block for keys k..k+3 (both queries), packed f32x2.
    auto scores = [&](int k, u64& sA01, u64& sA23, u64& sB01, u64& sB23) {
        sA01 = 0; sA23 = 0; sB01 = 0; sB23 = 0;
        #pragma unroll
        for (int j = 0; j < DD; j++) {
            ulonglong2 kv = *(const ulonglong2*)(sKT + j * NN + k);  // 4 keys @ dim j
            sA01 = fma2(kv.x, qpA[j], sA01);
            sA23 = fma2(kv.y, qpA[j], sA23);
            sB01 = fma2(kv.x, qpB[j], sB01);
            sB23 = fma2(kv.y, qpB[j], sB23);
        }
    };
    // exp + AV accumulation for a score block at keys k..k+3.
    u64 accA[8], accB[8];
    #pragma unroll
    for (int j = 0; j < 8; j++) { accA[j] = 0; accB[j] = 0; }
    u64 lpA = 0, lpB = 0;

    auto consume = [&](int k, u64 sA01, u64 sA23, u64 sB01, u64 sB23) {
        float a0, a1, a2, a3, b0, b1, b2, b3;
        unpack2(sA01, a0, a1); unpack2(sA23, a2, a3);
        unpack2(sB01, b0, b1); unpack2(sB23, b2, b3);
        u64 pA01 = pack2(fast_exp2(a0), fast_exp2(a1));
        u64 pA23 = pack2(fast_exp2(a2), fast_exp2(a3));
        u64 pB01 = pack2(fast_exp2(b0), fast_exp2(b1));
        u64 pB23 = pack2(fast_exp2(b2), fast_exp2(b3));
        lpA = add2(lpA, pA01); lpA = add2(lpA, pA23);
        lpB = add2(lpB, pB01); lpB = add2(lpB, pB23);
        #pragma unroll
        for (int j = 0; j < DD; j++) {
            ulonglong2 vv = *(const ulonglong2*)(sVT + j * NN + k);  // 4 keys @ dim j
            accA[j] = fma2(pA01, vv.x, accA[j]);
            accA[j] = fma2(pA23, vv.y, accA[j]);
            accB[j] = fma2(pB01, vv.x, accB[j]);
            accB[j] = fma2(pB23, vv.y, accB[j]);
        }
    };

    // ---- Software-pipelined main loop: scores(k+4) issue before consume(k) ----
    u64 cA01, cA23, cB01, cB23;
    scores(0, cA01, cA23, cB01, cB23);
    #pragma unroll 2
    for (int k = 0; k < NN - 4; k += 4) {
        u64 nA01, nA23, nB01, nB23;
        scores(k + 4, nA01, nA23, nB01, nB23);   // independent of current block
        consume(k, cA01, cA23, cB01, cB23);      // MUFU chain hides behind ^
        cA01 = nA01; cA23 = nA23; cB01 = nB01; cB23 = nB23;
    }
    consume(NN - 4, cA01, cA23, cB01, cB23);

    // ---- Epilogue: fold packed halves, normalize, store both query rows ----
    #pragma unroll
    for (int sel = 0; sel < 2; sel++) {
        const u64* acc = sel ? accB : accA;
        u64 lp = sel ? lpB : lpA;
        float l0, l1;
        unpack2(lp, l0, l1);
        const float inv = 1.0f / (l0 + l1);
        float o[8];
        #pragma unroll
        for (int j = 0; j < 8; j++) {
            float x, y;
            unpack2(acc[j], x, y);
            o[j] = (x + y) * inv;
        }
        float* op = g_mid + base + (size_t)(tid + sel * 256) * rowstride;
        ((float4*)op)[0] = make_float4(o[0], o[1], o[2], o[3]);
        ((float4*)op)[1] = make_float4(o[4], o[5], o[6], o[7]);
    }
}

// Output projection: y[r,:] = x[r,:] @ Wo^T + bo, R = B*N*T = 24576 rows.
// (R7 configuration, 16.5us: protected.)
#define PRPB 64
#define PXS 68
#define PWS 68

__global__ __launch_bounds__(256) void proj_kernel(
    const float* __restrict__ Wo, const float* __restrict__ bo, float* __restrict__ out)
{
    __shared__ float sWT[EE * PWS];
    __shared__ float sb[EE];
    __shared__ float sx[PRPB * PXS];

    const int tid = threadIdx.x;
    for (int idx = tid; idx < EE * EE; idx += 256) {
        int i = idx >> 6, j = idx & 63;
        sWT[j * PWS + i] = Wo[idx];
    }
    if (tid < EE) sb[tid] = bo[tid];

    const size_t rbase = (size_t)blockIdx.x * PRPB * EE;
    #pragma unroll
    for (int idx = tid * 4; idx < PRPB * EE; idx += 256 * 4) {
        float4 v = *(const float4*)(g_mid + rbase + idx);
        float* dst = sx + (idx >> 6) * PXS + (idx & 63);
        dst[0] = v.x; dst[1] = v.y; dst[2] = v.z; dst[3] = v.w;
    }
    __syncthreads();

    const int w = tid >> 5;
    const int lane = tid & 31;
    const int i0 = w * 8;

    u64 aA[4], aB[4];
    {
        u64 b01 = pack2(sb[i0 + 0], sb[i0 + 1]);
        u64 b23 = pack2(sb[i0 + 2], sb[i0 + 3]);
        u64 b45 = pack2(sb[i0 + 4], sb[i0 + 5]);
        u64 b67 = pack2(sb[i0 + 6], sb[i0 + 7]);
        aA[0] = b01; aA[1] = b23; aA[2] = b45; aA[3] = b67;
        aB[0] = b01; aB[1] = b23; aB[2] = b45; aB[3] = b67;
    }

    const float* xA = sx + lane * PXS;
    const float* xB = sx + (lane + 32) * PXS;
    #pragma unroll 4
    for (int j4 = 0; j4 < EE; j4 += 4) {
        float4 xa4 = *(const float4*)(xA + j4);
        float4 xb4 = *(const float4*)(xB + j4);
        const float xa[4] = {xa4.x, xa4.y, xa4.z, xa4.w};
        const float xb[4] = {xb4.x, xb4.y, xb4.z, xb4.w};
        #pragma unroll
        for (int jj = 0; jj < 4; jj++) {
            const ulonglong2* wp = (const ulonglong2*)(sWT + (j4 + jj) * PWS + i0);
            ulonglong2 wa = wp[0];
            ulonglong2 wb = wp[1];
            u64 xpa = pack2(xa[jj], xa[jj]);
            u64 xpb = pack2(xb[jj], xb[jj]);
            aA[0] = fma2(xpa, wa.x, aA[0]);
            aA[1] = fma2(xpa, wa.y, aA[1]);
            aA[2] = fma2(xpa, wb.x, aA[2]);
            aA[3] = fma2(xpa, wb.y, aA[3]);
            aB[0] = fma2(xpb, wa.x, aB[0]);
            aB[1] = fma2(xpb, wa.y, aB[1]);
            aB[2] = fma2(xpb, wb.x, aB[2]);
            aB[3] = fma2(xpb, wb.y, aB[3]);
        }
    }

    __syncthreads();
    #pragma unroll
    for (int r = 0; r < 2; r++) {
        const u64* a = r ? aB : aA;
        float* dst = sx + (lane + r * 32) * PXS + i0;
        #pragma unroll
        for (int c = 0; c < 4; c++) {
            float lo, hi;
            unpack2(a[c], lo, hi);
            dst[2 * c] = lo;
            dst[2 * c + 1] = hi;
        }
    }
    __syncthreads();
    #pragma unroll
    for (int idx = tid * 4; idx < PRPB * EE; idx += 256 * 4) {
        const float* src = sx + (idx >> 6) * PXS + (idx & 63);
        *(float4*)(out + rbase + idx) = make_float4(src[0], src[1], src[2], src[3]);
    }
}

extern "C" void kernel_launch(void* const* d_in, const int* in_sizes, int n_in,
                              void* d_out, int out_size)
{
    const float* values = (const float*)d_in[0];
    const float* keys   = (const float*)d_in[1];
    const float* query  = (const float*)d_in[2];
    const float* Wv     = (const float*)d_in[3];
    const float* Wk     = (const float*)d_in[4];
    const float* Wq     = (const float*)d_in[5];
    const float* Wo     = (const float*)d_in[6];
    const float* bo     = (const float*)d_in[7];

    attn_kernel<<<BN * TT * HH, 256>>>(values, keys, query, Wv, Wk, Wq);
    proj_kernel<<<BN * NN * TT / PRPB, 256>>>(Wo, bo, (float*)d_out);
}